// round 13
// baseline (speedup 1.0000x reference)
#include <cuda_runtime.h>
#include <math.h>

#define NN 16384
#define CC 64
#define KK 40
#define BUFD 12
#define SAMP 1024           // sample size for threshold (every 16th point)
#define CH 16               // candidate chunks in filter phase
#define CHSZ 1024           // candidates per chunk
#define SLOTS 112           // survivor capacity per (query, chunk)

// ---------------- scratch (device globals; no allocation allowed) ----------------
__device__ float  g_h[NN * CC];        // propagated features h = x@w_h + b_h
__device__ float4 g_s4[NN];            // learned coords (x,y,z,|s|^2)
__device__ int    g_knn[NN * KK];      // neighbor indices (unsorted top-40)
__device__ float  g_M[NN * 2 * CC];    // [mean | max] aggregation
__device__ float  g_t[NN * CC];        // xgn + x (input to BN2)
__device__ float  g_u[NN * CC];        // y + z (input to BN3)
__device__ float  g_sum2[CC], g_sumsq2[CC], g_sum3[CC], g_sumsq3[CC];
__device__ float  g_a2[CC], g_b2[CC], g_a3[CC], g_b3[CC];
__device__ float  g_tau[NN];                                   // per-query threshold
__device__ int    g_scnt[CH * NN];                             // survivor counts
__device__ unsigned long long g_sv[CH * SLOTS * NN];           // survivors: (score<<32)|idx, slot-major [plane][query]

// ---------------- K0: zero BN accumulators (must run every replay) ----------------
__global__ void k_zero() {
    int i = threadIdx.x;
    if (i < CC) { g_sum2[i] = 0.f; g_sumsq2[i] = 0.f; g_sum3[i] = 0.f; g_sumsq3[i] = 0.f; }
}

// ---------------- K1: h = x@w_h + b_h ; s = x@w_s ; store (s, |s|^2) ----------------
__global__ void __launch_bounds__(256) k_proj(
    const float* __restrict__ x, const float* __restrict__ w_h,
    const float* __restrict__ b_h, const float* __restrict__ w_s)
{
    __shared__ float wh[64 * 64];
    __shared__ float ws[64 * 4];
    __shared__ float bh[64];
    __shared__ float xr[4][64];
    int tid = threadIdx.x;
    for (int i = tid; i < 4096; i += 256) wh[i] = w_h[i];
    if (tid < 192) { int k = tid / 3, j = tid % 3; ws[k * 4 + j] = w_s[tid]; }
    if (tid < 64) bh[tid] = b_h[tid];
    __syncthreads();

    int c = tid & 63, sub = tid >> 6;
    int base = blockIdx.x * 128;
    for (int it = 0; it < 32; it++) {
        int n = base + it * 4 + sub;
        xr[sub][c] = x[n * 64 + c];
        __syncthreads();
        float acc = bh[c];
#pragma unroll
        for (int k = 0; k < 64; k++) acc = fmaf(xr[sub][k], wh[k * 64 + c], acc);
        g_h[n * 64 + c] = acc;
        if (c == 0) {
            float s0 = 0.f, s1 = 0.f, s2 = 0.f;
#pragma unroll
            for (int k = 0; k < 64; k++) {
                float xv = xr[sub][k];
                s0 = fmaf(xv, ws[k * 4 + 0], s0);
                s1 = fmaf(xv, ws[k * 4 + 1], s1);
                s2 = fmaf(xv, ws[k * 4 + 2], s2);
            }
            g_s4[n] = make_float4(s0, s1, s2, fmaf(s0, s0, fmaf(s1, s1, s2 * s2)));
        }
        __syncthreads();
    }
}

// ================= kNN phase 1: per-query threshold from 1024-point sample =================
// Scoring t = |c|^2 - 2 q.c (monotone in d^2 for fixed q).
// Per-thread 4-ary max-heap of 40 scores (no indices) over its partition of the sample.

extern __shared__ char dynraw[];

__device__ __forceinline__ void sift_s(float* hd, int tid, int pos, float d) {
#pragma unroll 3
    for (int lvl = 0; lvl < 3; lvl++) {
        int c1 = pos * 4 + 1;
        if (c1 >= KK) break;
        int mc = c1; float md = hd[c1 * 256 + tid];
        int e = KK - c1;
        if (e > 1) { float v = hd[(c1 + 1) * 256 + tid]; if (v > md) { md = v; mc = c1 + 1; } }
        if (e > 2) { float v = hd[(c1 + 2) * 256 + tid]; if (v > md) { md = v; mc = c1 + 2; } }
        if (e > 3) { float v = hd[(c1 + 3) * 256 + tid]; if (v > md) { md = v; mc = c1 + 3; } }
        if (md <= d) break;
        hd[pos * 256 + tid] = md;
        pos = mc;
    }
    hd[pos * 256 + tid] = d;
}

__global__ void __launch_bounds__(256) k_tau()
{
    float*  hd   = (float*)dynraw;                  // [40][256] @0      (40960 B)
    float*  bd   = (float*)(dynraw + 40960);        // [12][256] @40960  (12288 B)
    float4* tile = (float4*)(dynraw + 53248);       // [1024]    @53248  (16384 B)

    int tid = threadIdx.x;
    int q = tid >> 2, p = tid & 3;
    int Q = blockIdx.x * 64 + q;

    // load the sample (every 16th point) once
    for (int j = tid; j < SAMP; j += 256) tile[j] = g_s4[j * 16];
    __syncthreads();

    float4 qs = g_s4[Q];
    float m2x = -2.0f * qs.x, m2y = -2.0f * qs.y, m2z = -2.0f * qs.z;

    // prefill: first 40 sample candidates of this partition (locals p+4k, k<40 -> locals 0..159)
#pragma unroll 8
    for (int k = 0; k < KK; k++) {
        float4 cv = tile[p + 4 * k];
        hd[k * 256 + tid] = fmaf(cv.x, m2x, fmaf(cv.y, m2y, fmaf(cv.z, m2z, cv.w)));
    }
#pragma unroll
    for (int i2 = 9; i2 >= 0; i2--) {
        float d = hd[i2 * 256 + tid];
        sift_s(hd, tid, i2, d);
    }
    float worst = hd[tid];
    int bn = 0;

    for (int g8 = 5; g8 < SAMP / 32; g8++) {
        int base = g8 * 32 + p;
        float ts[8];
#pragma unroll
        for (int j = 0; j < 8; j++) {
            float4 cv = tile[base + 4 * j];
            ts[j] = fmaf(cv.x, m2x, fmaf(cv.y, m2y, fmaf(cv.z, m2z, cv.w)));
        }
#pragma unroll
        for (int j = 0; j < 8; j++) {
            if (ts[j] < worst) { bd[bn * 256 + tid] = ts[j]; bn++; }
        }
        if (__any_sync(0xffffffffu, bn >= 5)) {
            for (int b = 0; b < bn; b++) {
                float d = bd[b * 256 + tid];
                if (d < hd[tid]) sift_s(hd, tid, 0, d);
            }
            bn = 0;
            worst = hd[tid];
        }
    }
    for (int b = 0; b < bn; b++) {
        float d = bd[b * 256 + tid];
        if (d < hd[tid]) sift_s(hd, tid, 0, d);
    }
    __syncthreads();

    // merge 4 partitions into column tid (p==0); root = 40th best of sample = tau
    if (p == 0) {
        for (int o = 1; o < 4; o++) {
            for (int k = 0; k < KK; k++) {
                float d = hd[k * 256 + tid + o];
                if (d < hd[tid]) sift_s(hd, tid, 0, d);
            }
        }
        g_tau[Q] = hd[tid];
    }
}

// ================= kNN phase 2: filter all pairs against tau, 4 queries/thread =================
// Block = (query group of 1024) x (candidate chunk of 1024). Thread owns queries
// qb, qb+256, qb+512, qb+768 -> per-(query,chunk) survivor region is thread-exclusive (no atomics).
// Survivors stored slot-major: g_sv[(ch*SLOTS+slot)*NN + q] so phase 3 reads coalesce.

__global__ void __launch_bounds__(256) k_filter()
{
    __shared__ float4 tile[CHSZ];   // 16 KB
    int tid = threadIdx.x;
    int qg = blockIdx.x >> 4;
    int ch = blockIdx.x & 15;

    for (int j = tid; j < CHSZ; j += 256) tile[j] = g_s4[ch * CHSZ + j];

    int qk[4]; float m2x[4], m2y[4], m2z[4], tau[4]; int cnt[4];
#pragma unroll
    for (int k = 0; k < 4; k++) {
        qk[k] = qg * 1024 + tid + 256 * k;
        float4 qs = g_s4[qk[k]];
        m2x[k] = -2.0f * qs.x; m2y[k] = -2.0f * qs.y; m2z[k] = -2.0f * qs.z;
        tau[k] = g_tau[qk[k]];
        cnt[k] = 0;
    }
    __syncthreads();

#pragma unroll 2
    for (int j = 0; j < CHSZ; j++) {
        float4 cv = tile[j];
        unsigned jj = (unsigned)(ch * CHSZ + j);
#pragma unroll
        for (int k = 0; k < 4; k++) {
            float t = fmaf(cv.x, m2x[k], fmaf(cv.y, m2y[k], fmaf(cv.z, m2z[k], cv.w)));
            if (t <= tau[k] && cnt[k] < SLOTS) {
                unsigned long long v = ((unsigned long long)__float_as_uint(t) << 32) | jj;
                g_sv[(size_t)(ch * SLOTS + cnt[k]) * NN + qk[k]] = v;
                cnt[k]++;
            }
        }
    }
#pragma unroll
    for (int k = 0; k < 4; k++) g_scnt[ch * NN + qk[k]] = cnt[k];
}

// ================= kNN phase 3: exact top-40 of each query's survivors =================
// 64 threads/block, thread = one query; warp lanes = consecutive queries -> coalesced
// slot-synchronous reads. 4-ary max-heap (40 scores + u16 indices) in smem, stride 64.

__device__ __forceinline__ void sift3(float* hd, unsigned short* hi, int tid, int pos,
                                      float d, unsigned short j) {
#pragma unroll 3
    for (int lvl = 0; lvl < 3; lvl++) {
        int c1 = pos * 4 + 1;
        if (c1 >= KK) break;
        int mc = c1; float md = hd[c1 * 64 + tid];
        int e = KK - c1;
        if (e > 1) { float v = hd[(c1 + 1) * 64 + tid]; if (v > md) { md = v; mc = c1 + 1; } }
        if (e > 2) { float v = hd[(c1 + 2) * 64 + tid]; if (v > md) { md = v; mc = c1 + 2; } }
        if (e > 3) { float v = hd[(c1 + 3) * 64 + tid]; if (v > md) { md = v; mc = c1 + 3; } }
        if (md <= d) break;
        hd[pos * 64 + tid] = md; hi[pos * 64 + tid] = hi[mc * 64 + tid];
        pos = mc;
    }
    hd[pos * 64 + tid] = d; hi[pos * 64 + tid] = j;
}

__global__ void __launch_bounds__(64) k_select()
{
    __shared__ float          hd[KK * 64];
    __shared__ unsigned short hi[KK * 64];
    int tid = threadIdx.x;
    int q = blockIdx.x * 64 + tid;

#pragma unroll 8
    for (int k = 0; k < KK; k++) { hd[k * 64 + tid] = 3.4e38f; hi[k * 64 + tid] = 0; }
    float worst = 3.4e38f;

    for (int c = 0; c < CH; c++) {
        int cnt = g_scnt[c * NN + q];
        int mc = (int)__reduce_max_sync(0xffffffffu, (unsigned)cnt);
        const unsigned long long* base = g_sv + (size_t)(c * SLOTS) * NN + q;
        for (int s = 0; s < mc; s++) {
            if (s < cnt) {
                unsigned long long v = base[(size_t)s * NN];
                float t = __uint_as_float((unsigned)(v >> 32));
                if (t < worst) {
                    sift3(hd, hi, tid, 0, t, (unsigned short)(v & 0xFFFFu));
                    worst = hd[tid];
                }
            }
        }
    }
    for (int r = 0; r < KK; r++) g_knn[q * KK + r] = (int)hi[r * 64 + tid];
}

// ---------------- K3a: edge weights + mean/max message aggregation ----------------
__global__ void __launch_bounds__(256) k_gather()
{
    __shared__ int   jl[4][KK];
    __shared__ float wl[4][KK];
    int tid = threadIdx.x;
    int g = tid >> 6, c = tid & 63;
    int i = blockIdx.x * 4 + g;
    if (c < KK) {
        int j = g_knn[i * KK + c];
        float4 sj = g_s4[j];
        float4 si_ = g_s4[i];
        float dx = si_.x - sj.x, dy = si_.y - sj.y, dz = si_.z - sj.z;
        float d2 = dx * dx + dy * dy + dz * dz;
        jl[g][c] = j;
        wl[g][c] = expf(-(d2 + 1e-6f));
    }
    __syncthreads();
    float sum = 0.f, mx = -3.4e38f;
#pragma unroll
    for (int k = 0; k < KK; k++) {
        float m = wl[g][k] * g_h[jl[g][k] * 64 + c];
        sum += m;
        mx = fmaxf(mx, m);
    }
    g_M[i * 128 + c] = sum * (1.0f / KK);
    g_M[i * 128 + 64 + c] = mx;
}

// ---------------- K3b: t = [mean|max|x] @ w_lin + b_lin + x ; BN2 partial sums ----------------
__global__ void __launch_bounds__(256) k_lin(
    const float* __restrict__ x, const float* __restrict__ w_lin,
    const float* __restrict__ b_lin)
{
    float* wl = (float*)dynraw;              // [192*64]
    float* ar = (float*)dynraw + 192 * 64;   // [4][192]
    __shared__ float bl[64];
    __shared__ float red[2][4][64];
    int tid = threadIdx.x;
    for (int i = tid; i < 192 * 64; i += 256) wl[i] = w_lin[i];
    if (tid < 64) bl[tid] = b_lin[tid];
    __syncthreads();

    int c = tid & 63, sub = tid >> 6;
    int base = blockIdx.x * 128;
    float psum = 0.f, psq = 0.f;
    for (int it = 0; it < 32; it++) {
        int n = base + it * 4 + sub;
        ar[sub * 192 + c]       = g_M[n * 128 + c];
        ar[sub * 192 + 64 + c]  = g_M[n * 128 + 64 + c];
        ar[sub * 192 + 128 + c] = x[n * 64 + c];
        __syncthreads();
        float acc = bl[c] + ar[sub * 192 + 128 + c];   // + residual x
#pragma unroll
        for (int f = 0; f < 192; f++) acc = fmaf(ar[sub * 192 + f], wl[f * 64 + c], acc);
        g_t[n * 64 + c] = acc;
        psum += acc;
        psq = fmaf(acc, acc, psq);
        __syncthreads();
    }
    red[0][sub][c] = psum;
    red[1][sub][c] = psq;
    __syncthreads();
    if (sub == 0) {
        float s  = red[0][0][c] + red[0][1][c] + red[0][2][c] + red[0][3][c];
        float s2 = red[1][0][c] + red[1][1][c] + red[1][2][c] + red[1][3][c];
        atomicAdd(&g_sum2[c], s);
        atomicAdd(&g_sumsq2[c], s2);
    }
}

// ---------------- K4/K6: finalize BN affine params ----------------
__global__ void k_bnfin(const float* __restrict__ gamma, const float* __restrict__ beta, int which)
{
    int c = threadIdx.x;
    if (c < CC) {
        float s  = which ? g_sum3[c]   : g_sum2[c];
        float s2 = which ? g_sumsq3[c] : g_sumsq2[c];
        float mu  = s * (1.0f / NN);
        float var = s2 * (1.0f / NN) - mu * mu;
        float ai = gamma[c] * rsqrtf(var + 1e-5f);
        float bi = beta[c] - ai * mu;
        if (which) { g_a3[c] = ai; g_b3[c] = bi; }
        else       { g_a2[c] = ai; g_b2[c] = bi; }
    }
}

// ---------------- K5: y = BN2(t); z = elu(y@w_p1+b_p1)@w_p2+b_p2; u = y+z ; BN3 sums ----------------
__global__ void __launch_bounds__(256) k_mlp(
    const float* __restrict__ w_p1, const float* __restrict__ b_p1,
    const float* __restrict__ w_p2, const float* __restrict__ b_p2)
{
    __shared__ float w1[4096], w2[4096], b1s[64], b2s[64], aas[64], bbs[64];
    __shared__ float yr[4][64], vr[4][64];
    __shared__ float red[2][4][64];
    int tid = threadIdx.x;
    for (int i = tid; i < 4096; i += 256) { w1[i] = w_p1[i]; w2[i] = w_p2[i]; }
    if (tid < 64) { b1s[tid] = b_p1[tid]; b2s[tid] = b_p2[tid]; aas[tid] = g_a2[tid]; bbs[tid] = g_b2[tid]; }
    __syncthreads();

    int c = tid & 63, sub = tid >> 6;
    int base = blockIdx.x * 128;
    float psum = 0.f, psq = 0.f;
    for (int it = 0; it < 32; it++) {
        int n = base + it * 4 + sub;
        float yv = fmaf(aas[c], g_t[n * 64 + c], bbs[c]);
        yr[sub][c] = yv;
        __syncthreads();
        float a1 = b1s[c];
#pragma unroll
        for (int k = 0; k < 64; k++) a1 = fmaf(yr[sub][k], w1[k * 64 + c], a1);
        float v = a1 > 0.f ? a1 : expm1f(a1);
        vr[sub][c] = v;
        __syncthreads();
        float a2v = b2s[c];
#pragma unroll
        for (int k = 0; k < 64; k++) a2v = fmaf(vr[sub][k], w2[k * 64 + c], a2v);
        float u = yv + a2v;
        g_u[n * 64 + c] = u;
        psum += u;
        psq = fmaf(u, u, psq);
        __syncthreads();
    }
    red[0][sub][c] = psum;
    red[1][sub][c] = psq;
    __syncthreads();
    if (sub == 0) {
        float s  = red[0][0][c] + red[0][1][c] + red[0][2][c] + red[0][3][c];
        float s2 = red[1][0][c] + red[1][1][c] + red[1][2][c] + red[1][3][c];
        atomicAdd(&g_sum3[c], s);
        atomicAdd(&g_sumsq3[c], s2);
    }
}

// ---------------- K7: out = BN3(u) ----------------
__global__ void __launch_bounds__(256) k_out(float* __restrict__ out)
{
    int idx = blockIdx.x * 256 + threadIdx.x;   // over N*C/4 float4
    const float4* u4 = (const float4*)g_u;
    float4 v = u4[idx];
    int c = (idx * 4) & 63;
    float4 r;
    r.x = fmaf(g_a3[c + 0], v.x, g_b3[c + 0]);
    r.y = fmaf(g_a3[c + 1], v.y, g_b3[c + 1]);
    r.z = fmaf(g_a3[c + 2], v.z, g_b3[c + 2]);
    r.w = fmaf(g_a3[c + 3], v.w, g_b3[c + 3]);
    ((float4*)out)[idx] = r;
}

// ---------------- launch ----------------
extern "C" void kernel_launch(void* const* d_in, const int* in_sizes, int n_in,
                              void* d_out, int out_size)
{
    const float* x     = (const float*)d_in[0];
    const float* w_s   = (const float*)d_in[1];
    const float* w_h   = (const float*)d_in[2];
    const float* b_h   = (const float*)d_in[3];
    const float* w_lin = (const float*)d_in[4];
    const float* b_lin = (const float*)d_in[5];
    const float* w_p1  = (const float*)d_in[6];
    const float* b_p1  = (const float*)d_in[7];
    const float* w_p2  = (const float*)d_in[8];
    const float* b_p2  = (const float*)d_in[9];
    const float* gamma2 = (const float*)d_in[10];
    const float* beta2  = (const float*)d_in[11];
    const float* gamma3 = (const float*)d_in[12];
    const float* beta3  = (const float*)d_in[13];
    float* out = (float*)d_out;

    const int tau_smem = 40960 + 12288 + 16384;          // 69632 B
    const int lin_smem = (192 * 64 + 4 * 192) * 4;       // 52224 B
    cudaFuncSetAttribute(k_tau, cudaFuncAttributeMaxDynamicSharedMemorySize, tau_smem);
    cudaFuncSetAttribute(k_lin, cudaFuncAttributeMaxDynamicSharedMemorySize, lin_smem);

    k_zero<<<1, 64>>>();
    k_proj<<<128, 256>>>(x, w_h, b_h, w_s);
    k_tau<<<256, 256, tau_smem>>>();
    k_filter<<<256, 256>>>();
    k_select<<<256, 64>>>();
    k_gather<<<NN / 4, 256>>>();
    k_lin<<<128, 256, lin_smem>>>(x, w_lin, b_lin);
    k_bnfin<<<1, 64>>>(gamma2, beta2, 0);
    k_mlp<<<128, 256>>>(w_p1, b_p1, w_p2, b_p2);
    k_bnfin<<<1, 64>>>(gamma3, beta3, 1);
    k_out<<<(NN * CC / 4) / 256, 256>>>(out);
}

// round 14
// speedup vs baseline: 2.1935x; 2.1935x over previous
#include <cuda_runtime.h>
#include <math.h>

#define NN 16384
#define CC 64
#define KK 40
#define QW 8            // queries (= warps) per k_knn block

// ---------------- scratch (device globals; no allocation allowed) ----------------
__device__ float  g_h[NN * CC];        // propagated features h = x@w_h + b_h
__device__ float4 g_s4[NN];            // learned coords (x,y,z,|s|^2)
__device__ int    g_knn[NN * KK];      // neighbor indices (unsorted top-40)
__device__ float  g_M[NN * 2 * CC];    // [mean | max] aggregation
__device__ float  g_t[NN * CC];        // xgn + x (input to BN2)
__device__ float  g_u[NN * CC];        // y + z (input to BN3)
__device__ float  g_sum2[CC], g_sumsq2[CC], g_sum3[CC], g_sumsq3[CC];
__device__ float  g_a2[CC], g_b2[CC], g_a3[CC], g_b3[CC];

// ---------------- K0: zero BN accumulators (must run every replay) ----------------
__global__ void k_zero() {
    int i = threadIdx.x;
    if (i < CC) { g_sum2[i] = 0.f; g_sumsq2[i] = 0.f; g_sum3[i] = 0.f; g_sumsq3[i] = 0.f; }
}

// ---------------- K1: h = x@w_h + b_h ; s = x@w_s ; store (s, |s|^2) ----------------
__global__ void __launch_bounds__(256) k_proj(
    const float* __restrict__ x, const float* __restrict__ w_h,
    const float* __restrict__ b_h, const float* __restrict__ w_s)
{
    __shared__ float wh[64 * 64];
    __shared__ float ws[64 * 4];
    __shared__ float bh[64];
    __shared__ float xr[4][64];
    int tid = threadIdx.x;
    for (int i = tid; i < 4096; i += 256) wh[i] = w_h[i];
    if (tid < 192) { int k = tid / 3, j = tid % 3; ws[k * 4 + j] = w_s[tid]; }
    if (tid < 64) bh[tid] = b_h[tid];
    __syncthreads();

    int c = tid & 63, sub = tid >> 6;
    int base = blockIdx.x * 128;
    for (int it = 0; it < 32; it++) {
        int n = base + it * 4 + sub;
        xr[sub][c] = x[n * 64 + c];
        __syncthreads();
        float acc = bh[c];
#pragma unroll
        for (int k = 0; k < 64; k++) acc = fmaf(xr[sub][k], wh[k * 64 + c], acc);
        g_h[n * 64 + c] = acc;
        if (c == 0) {
            float s0 = 0.f, s1 = 0.f, s2 = 0.f;
#pragma unroll
            for (int k = 0; k < 64; k++) {
                float xv = xr[sub][k];
                s0 = fmaf(xv, ws[k * 4 + 0], s0);
                s1 = fmaf(xv, ws[k * 4 + 1], s1);
                s2 = fmaf(xv, ws[k * 4 + 2], s2);
            }
            g_s4[n] = make_float4(s0, s1, s2, fmaf(s0, s0, fmaf(s1, s1, s2 * s2)));
        }
        __syncthreads();
    }
}

// ================= K2: warp-cooperative exact kNN =================
// One warp per query. 40-entry ascending sorted list lives in REGISTERS across
// the warp: lane L holds list positions L (v0,i0) and 32+L (v1,i1; valid L<8).
// Scoring t = |c|^2 - 2 q.c (monotone in d^2 for fixed q).
// Insert is warp-uniform: 2 ballots give the rank, shuffles shift the tail up.
// Strict '<' gate + placement after equal entries == first-seen-kept tie rule.

__device__ __forceinline__ void winsert(float t, int j, int lane,
                                        float& v0, int& i0, float& v1, int& i1,
                                        float& worst)
{
    const unsigned F = 0xffffffffu;
    unsigned b0 = __ballot_sync(F, v0 <= t);
    unsigned b1 = __ballot_sync(F, (lane < 8) && (v1 <= t));
    int pos = __popc(b0) + __popc(b1);          // rank: after equal entries
    float su0 = __shfl_up_sync(F, v0, 1); int sj0 = __shfl_up_sync(F, i0, 1);
    float su1 = __shfl_up_sync(F, v1, 1); int sj1 = __shfl_up_sync(F, i1, 1);
    float b31 = __shfl_sync(F, v0, 31);   int c31 = __shfl_sync(F, i0, 31);
    if (lane > pos)       { v0 = su0; i0 = sj0; }
    else if (lane == pos) { v0 = t;   i0 = j;   }
    int p1 = 32 + lane;
    float nv1 = (lane == 0) ? b31 : su1;
    int   nj1 = (lane == 0) ? c31 : sj1;
    if (p1 > pos)         { v1 = nv1; i1 = nj1; }
    else if (p1 == pos)   { v1 = t;   i1 = j;   }
    worst = __shfl_sync(F, v1, 7);              // list position 39
}

__global__ void __launch_bounds__(256) k_knn()
{
    __shared__ float4 tile[2048];   // 32 KB candidate chunk, shared by 8 query-warps
    const unsigned F = 0xffffffffu;
    int tid = threadIdx.x;
    int lane = tid & 31, w = tid >> 5;
    int Q = blockIdx.x * QW + w;
    float4 qs = g_s4[Q];
    float m2x = -2.0f * qs.x, m2y = -2.0f * qs.y, m2z = -2.0f * qs.z;

    float v0 = 3.4e38f, v1 = 3.4e38f;
    int   i0 = 0,       i1 = 0;
    float worst = 3.4e38f;

    for (int c0 = 0; c0 < NN; c0 += 2048) {
        __syncthreads();
#pragma unroll
        for (int j = 0; j < 8; j++) tile[tid + 256 * j] = g_s4[c0 + tid + 256 * j];
        __syncthreads();
        for (int s = 0; s < 2048; s += 64) {
            float4 ca = tile[s + lane];
            float4 cb = tile[s + 32 + lane];
            float ta = fmaf(ca.x, m2x, fmaf(ca.y, m2y, fmaf(ca.z, m2z, ca.w)));
            float tb = fmaf(cb.x, m2x, fmaf(cb.y, m2y, fmaf(cb.z, m2z, cb.w)));
            unsigned ma = __ballot_sync(F, ta < worst);
            while (ma) {
                int src = __ffs(ma) - 1; ma &= ma - 1;
                float t = __shfl_sync(F, ta, src);
                if (t < worst) winsert(t, c0 + s + src, lane, v0, i0, v1, i1, worst);
            }
            unsigned mb = __ballot_sync(F, tb < worst);
            while (mb) {
                int src = __ffs(mb) - 1; mb &= mb - 1;
                float t = __shfl_sync(F, tb, src);
                if (t < worst) winsert(t, c0 + s + 32 + src, lane, v0, i0, v1, i1, worst);
            }
        }
    }
    // write the 40 indices (order irrelevant for mean/max aggregation)
    g_knn[Q * KK + lane] = i0;
    if (lane < 8) g_knn[Q * KK + 32 + lane] = i1;
}

// ---------------- K3a: edge weights + mean/max message aggregation ----------------
__global__ void __launch_bounds__(256) k_gather()
{
    __shared__ int   jl[4][KK];
    __shared__ float wl[4][KK];
    int tid = threadIdx.x;
    int g = tid >> 6, c = tid & 63;
    int i = blockIdx.x * 4 + g;
    if (c < KK) {
        int j = g_knn[i * KK + c];
        float4 sj = g_s4[j];
        float4 si_ = g_s4[i];
        float dx = si_.x - sj.x, dy = si_.y - sj.y, dz = si_.z - sj.z;
        float d2 = dx * dx + dy * dy + dz * dz;
        jl[g][c] = j;
        wl[g][c] = expf(-(d2 + 1e-6f));
    }
    __syncthreads();
    float sum = 0.f, mx = -3.4e38f;
#pragma unroll
    for (int k = 0; k < KK; k++) {
        float m = wl[g][k] * g_h[jl[g][k] * 64 + c];
        sum += m;
        mx = fmaxf(mx, m);
    }
    g_M[i * 128 + c] = sum * (1.0f / KK);
    g_M[i * 128 + 64 + c] = mx;
}

// ---------------- K3b: t = [mean|max|x] @ w_lin + b_lin + x ; BN2 partial sums ----------------
extern __shared__ char dynraw[];

__global__ void __launch_bounds__(256) k_lin(
    const float* __restrict__ x, const float* __restrict__ w_lin,
    const float* __restrict__ b_lin)
{
    float* wl = (float*)dynraw;              // [192*64]
    float* ar = (float*)dynraw + 192 * 64;   // [4][192]
    __shared__ float bl[64];
    __shared__ float red[2][4][64];
    int tid = threadIdx.x;
    for (int i = tid; i < 192 * 64; i += 256) wl[i] = w_lin[i];
    if (tid < 64) bl[tid] = b_lin[tid];
    __syncthreads();

    int c = tid & 63, sub = tid >> 6;
    int base = blockIdx.x * 128;
    float psum = 0.f, psq = 0.f;
    for (int it = 0; it < 32; it++) {
        int n = base + it * 4 + sub;
        ar[sub * 192 + c]       = g_M[n * 128 + c];
        ar[sub * 192 + 64 + c]  = g_M[n * 128 + 64 + c];
        ar[sub * 192 + 128 + c] = x[n * 64 + c];
        __syncthreads();
        float acc = bl[c] + ar[sub * 192 + 128 + c];   // + residual x
#pragma unroll
        for (int f = 0; f < 192; f++) acc = fmaf(ar[sub * 192 + f], wl[f * 64 + c], acc);
        g_t[n * 64 + c] = acc;
        psum += acc;
        psq = fmaf(acc, acc, psq);
        __syncthreads();
    }
    red[0][sub][c] = psum;
    red[1][sub][c] = psq;
    __syncthreads();
    if (sub == 0) {
        float s  = red[0][0][c] + red[0][1][c] + red[0][2][c] + red[0][3][c];
        float s2 = red[1][0][c] + red[1][1][c] + red[1][2][c] + red[1][3][c];
        atomicAdd(&g_sum2[c], s);
        atomicAdd(&g_sumsq2[c], s2);
    }
}

// ---------------- K4/K6: finalize BN affine params ----------------
__global__ void k_bnfin(const float* __restrict__ gamma, const float* __restrict__ beta, int which)
{
    int c = threadIdx.x;
    if (c < CC) {
        float s  = which ? g_sum3[c]   : g_sum2[c];
        float s2 = which ? g_sumsq3[c] : g_sumsq2[c];
        float mu  = s * (1.0f / NN);
        float var = s2 * (1.0f / NN) - mu * mu;
        float ai = gamma[c] * rsqrtf(var + 1e-5f);
        float bi = beta[c] - ai * mu;
        if (which) { g_a3[c] = ai; g_b3[c] = bi; }
        else       { g_a2[c] = ai; g_b2[c] = bi; }
    }
}

// ---------------- K5: y = BN2(t); z = elu(y@w_p1+b_p1)@w_p2+b_p2; u = y+z ; BN3 sums ----------------
__global__ void __launch_bounds__(256) k_mlp(
    const float* __restrict__ w_p1, const float* __restrict__ b_p1,
    const float* __restrict__ w_p2, const float* __restrict__ b_p2)
{
    __shared__ float w1[4096], w2[4096], b1s[64], b2s[64], aas[64], bbs[64];
    __shared__ float yr[4][64], vr[4][64];
    __shared__ float red[2][4][64];
    int tid = threadIdx.x;
    for (int i = tid; i < 4096; i += 256) { w1[i] = w_p1[i]; w2[i] = w_p2[i]; }
    if (tid < 64) { b1s[tid] = b_p1[tid]; b2s[tid] = b_p2[tid]; aas[tid] = g_a2[tid]; bbs[tid] = g_b2[tid]; }
    __syncthreads();

    int c = tid & 63, sub = tid >> 6;
    int base = blockIdx.x * 128;
    float psum = 0.f, psq = 0.f;
    for (int it = 0; it < 32; it++) {
        int n = base + it * 4 + sub;
        float yv = fmaf(aas[c], g_t[n * 64 + c], bbs[c]);
        yr[sub][c] = yv;
        __syncthreads();
        float a1 = b1s[c];
#pragma unroll
        for (int k = 0; k < 64; k++) a1 = fmaf(yr[sub][k], w1[k * 64 + c], a1);
        float v = a1 > 0.f ? a1 : expm1f(a1);
        vr[sub][c] = v;
        __syncthreads();
        float a2v = b2s[c];
#pragma unroll
        for (int k = 0; k < 64; k++) a2v = fmaf(vr[sub][k], w2[k * 64 + c], a2v);
        float u = yv + a2v;
        g_u[n * 64 + c] = u;
        psum += u;
        psq = fmaf(u, u, psq);
        __syncthreads();
    }
    red[0][sub][c] = psum;
    red[1][sub][c] = psq;
    __syncthreads();
    if (sub == 0) {
        float s  = red[0][0][c] + red[0][1][c] + red[0][2][c] + red[0][3][c];
        float s2 = red[1][0][c] + red[1][1][c] + red[1][2][c] + red[1][3][c];
        atomicAdd(&g_sum3[c], s);
        atomicAdd(&g_sumsq3[c], s2);
    }
}

// ---------------- K7: out = BN3(u) ----------------
__global__ void __launch_bounds__(256) k_out(float* __restrict__ out)
{
    int idx = blockIdx.x * 256 + threadIdx.x;   // over N*C/4 float4
    const float4* u4 = (const float4*)g_u;
    float4 v = u4[idx];
    int c = (idx * 4) & 63;
    float4 r;
    r.x = fmaf(g_a3[c + 0], v.x, g_b3[c + 0]);
    r.y = fmaf(g_a3[c + 1], v.y, g_b3[c + 1]);
    r.z = fmaf(g_a3[c + 2], v.z, g_b3[c + 2]);
    r.w = fmaf(g_a3[c + 3], v.w, g_b3[c + 3]);
    ((float4*)out)[idx] = r;
}

// ---------------- launch ----------------
extern "C" void kernel_launch(void* const* d_in, const int* in_sizes, int n_in,
                              void* d_out, int out_size)
{
    const float* x     = (const float*)d_in[0];
    const float* w_s   = (const float*)d_in[1];
    const float* w_h   = (const float*)d_in[2];
    const float* b_h   = (const float*)d_in[3];
    const float* w_lin = (const float*)d_in[4];
    const float* b_lin = (const float*)d_in[5];
    const float* w_p1  = (const float*)d_in[6];
    const float* b_p1  = (const float*)d_in[7];
    const float* w_p2  = (const float*)d_in[8];
    const float* b_p2  = (const float*)d_in[9];
    const float* gamma2 = (const float*)d_in[10];
    const float* beta2  = (const float*)d_in[11];
    const float* gamma3 = (const float*)d_in[12];
    const float* beta3  = (const float*)d_in[13];
    float* out = (float*)d_out;

    const int lin_smem = (192 * 64 + 4 * 192) * 4;       // 52224 B
    cudaFuncSetAttribute(k_lin, cudaFuncAttributeMaxDynamicSharedMemorySize, lin_smem);

    k_zero<<<1, 64>>>();
    k_proj<<<128, 256>>>(x, w_h, b_h, w_s);
    k_knn<<<NN / QW, 256>>>();
    k_gather<<<NN / 4, 256>>>();
    k_lin<<<128, 256, lin_smem>>>(x, w_lin, b_lin);
    k_bnfin<<<1, 64>>>(gamma2, beta2, 0);
    k_mlp<<<128, 256>>>(w_p1, b_p1, w_p2, b_p2);
    k_bnfin<<<1, 64>>>(gamma3, beta3, 1);
    k_out<<<(NN * CC / 4) / 256, 256>>>(out);
}

// round 17
// speedup vs baseline: 2.4414x; 1.1130x over previous
#include <cuda_runtime.h>
#include <math.h>

#define NN 16384
#define CC 64
#define KK 40
#define NBIN 512
#define QW 8            // queries (= warps) per k_knn block

// ---------------- scratch (device globals; no allocation allowed) ----------------
__device__ float  g_h[NN * CC];        // propagated features h = x@w_h + b_h
__device__ float4 g_s4[NN];            // learned coords (x,y,z,|s|^2)
__device__ float4 g_ss[NN];            // coords bin-sorted by x
__device__ int    g_sid[NN];           // original index of sorted position
__device__ int    g_knn[NN * KK];      // neighbor indices (unsorted top-40)
__device__ float  g_M[NN * 2 * CC];    // [mean | max] aggregation
__device__ float  g_t[NN * CC];        // xgn + x (input to BN2)
__device__ float  g_u[NN * CC];        // y + z (input to BN3)
__device__ float  g_sum2[CC], g_sumsq2[CC], g_sum3[CC], g_sumsq3[CC];
__device__ float  g_a2[CC], g_b2[CC], g_a3[CC], g_b3[CC];
__device__ unsigned g_xminK, g_xmaxK;
__device__ int    g_hist[NBIN], g_cursor[NBIN];

// order-preserving float<->uint key
__device__ __forceinline__ unsigned fkey(float f) {
    unsigned b = __float_as_uint(f);
    return (b & 0x80000000u) ? ~b : (b | 0x80000000u);
}
__device__ __forceinline__ float funkey(unsigned k) {
    unsigned b = (k & 0x80000000u) ? (k & 0x7FFFFFFFu) : ~k;
    return __uint_as_float(b);
}

// ---------------- K0: zero accumulators (must run every replay) ----------------
__global__ void k_zero() {
    int i = threadIdx.x;
    if (i < CC) { g_sum2[i] = 0.f; g_sumsq2[i] = 0.f; g_sum3[i] = 0.f; g_sumsq3[i] = 0.f; }
    if (i < NBIN) g_hist[i] = 0;
    if (i == 0) { g_xminK = 0xFFFFFFFFu; g_xmaxK = 0u; }
}

// ---------------- K1: h = x@w_h + b_h ; s = x@w_s ; (s,|s|^2) + x-range atomics ----------------
__global__ void __launch_bounds__(256) k_proj(
    const float* __restrict__ x, const float* __restrict__ w_h,
    const float* __restrict__ b_h, const float* __restrict__ w_s)
{
    __shared__ float wh[64 * 64];
    __shared__ float ws[64 * 4];
    __shared__ float bh[64];
    __shared__ float xr[4][64];
    int tid = threadIdx.x;
    for (int i = tid; i < 4096; i += 256) wh[i] = w_h[i];
    if (tid < 192) { int k = tid / 3, j = tid % 3; ws[k * 4 + j] = w_s[tid]; }
    if (tid < 64) bh[tid] = b_h[tid];
    __syncthreads();

    int c = tid & 63, sub = tid >> 6;
    int base = blockIdx.x * 128;
    unsigned lmin = 0xFFFFFFFFu, lmax = 0u;
    for (int it = 0; it < 32; it++) {
        int n = base + it * 4 + sub;
        xr[sub][c] = x[n * 64 + c];
        __syncthreads();
        float acc = bh[c];
#pragma unroll
        for (int k = 0; k < 64; k++) acc = fmaf(xr[sub][k], wh[k * 64 + c], acc);
        g_h[n * 64 + c] = acc;
        if (c == 0) {
            float s0 = 0.f, s1 = 0.f, s2 = 0.f;
#pragma unroll
            for (int k = 0; k < 64; k++) {
                float xv = xr[sub][k];
                s0 = fmaf(xv, ws[k * 4 + 0], s0);
                s1 = fmaf(xv, ws[k * 4 + 1], s1);
                s2 = fmaf(xv, ws[k * 4 + 2], s2);
            }
            g_s4[n] = make_float4(s0, s1, s2, fmaf(s0, s0, fmaf(s1, s1, s2 * s2)));
            unsigned k0 = fkey(s0);
            lmin = min(lmin, k0); lmax = max(lmax, k0);
        }
        __syncthreads();
    }
    if (c == 0) { atomicMin(&g_xminK, lmin); atomicMax(&g_xmaxK, lmax); }
}

// ---------------- bin-sort by x: histogram -> prefix -> scatter ----------------
__device__ __forceinline__ int xbin(float xv, float xmin, float inv) {
    int b = (int)((xv - xmin) * inv);
    return min(NBIN - 1, max(0, b));
}

__global__ void __launch_bounds__(256) k_bins() {
    int i = blockIdx.x * 256 + threadIdx.x;
    float xmin = funkey(g_xminK), xmax = funkey(g_xmaxK);
    float inv = (float)NBIN / (xmax - xmin + 1e-20f);
    atomicAdd(&g_hist[xbin(g_s4[i].x, xmin, inv)], 1);
}

__global__ void __launch_bounds__(NBIN) k_scan() {
    __shared__ int tmp[NBIN];
    int t = threadIdx.x;
    int h = g_hist[t];
    tmp[t] = h;
    __syncthreads();
    for (int o = 1; o < NBIN; o <<= 1) {
        int v = (t >= o) ? tmp[t - o] : 0;
        __syncthreads();
        tmp[t] += v;
        __syncthreads();
    }
    g_cursor[t] = tmp[t] - h;   // exclusive prefix
}

__global__ void __launch_bounds__(256) k_scatter() {
    int i = blockIdx.x * 256 + threadIdx.x;
    float xmin = funkey(g_xminK), xmax = funkey(g_xmaxK);
    float inv = (float)NBIN / (xmax - xmin + 1e-20f);
    float4 s = g_s4[i];
    int pos = atomicAdd(&g_cursor[xbin(s.x, xmin, inv)], 1);
    g_ss[pos] = s;
    g_sid[pos] = i;
}

// ================= K2: warp-cooperative exact kNN over x-bin-sorted window =================
// One warp per sorted position r. Expand left/right in 32-candidate chunks.
// Array is BIN-sorted: within a bin x is unordered, so every unscanned point to
// the right satisfies x >= x_edge - binw (edge in bin be; further points in bins
// >= be). Conservative exact stop: (dx_edge - binw)^2 >= worst_d2 (with margin).
// Scoring t = |c|^2 - 2 q.c = d^2 - |q|^2 (monotone); worst_d2 = worst_t + |q|^2.
// 40-entry ascending sorted list in registers across the warp (lane L holds
// positions L and 32+L). Strict '<' gate, placed after equals = first-seen-kept.

__device__ __forceinline__ void winsert(float t, int j, int lane,
                                        float& v0, int& i0, float& v1, int& i1,
                                        float& worst)
{
    const unsigned F = 0xffffffffu;
    unsigned b0 = __ballot_sync(F, v0 <= t);
    unsigned b1 = __ballot_sync(F, (lane < 8) && (v1 <= t));
    int pos = __popc(b0) + __popc(b1);
    float su0 = __shfl_up_sync(F, v0, 1); int sj0 = __shfl_up_sync(F, i0, 1);
    float su1 = __shfl_up_sync(F, v1, 1); int sj1 = __shfl_up_sync(F, i1, 1);
    float b31 = __shfl_sync(F, v0, 31);   int c31 = __shfl_sync(F, i0, 31);
    if (lane > pos)       { v0 = su0; i0 = sj0; }
    else if (lane == pos) { v0 = t;   i0 = j;   }
    int p1 = 32 + lane;
    float nv1 = (lane == 0) ? b31 : su1;
    int   nj1 = (lane == 0) ? c31 : sj1;
    if (p1 > pos)         { v1 = nv1; i1 = nj1; }
    else if (p1 == pos)   { v1 = t;   i1 = j;   }
    worst = __shfl_sync(F, v1, 7);
}

__global__ void __launch_bounds__(256) k_knn()
{
    const unsigned F = 0xffffffffu;
    int lane = threadIdx.x & 31, w = threadIdx.x >> 5;
    int r = blockIdx.x * QW + w;
    float4 qv = g_ss[r];
    int Qo = g_sid[r];
    float qx = qv.x, qw2 = qv.w;
    float m2x = -2.0f * qv.x, m2y = -2.0f * qv.y, m2z = -2.0f * qv.z;

    float xmin = funkey(g_xminK), xmax = funkey(g_xmaxK);
    float binw = (xmax - xmin + 1e-20f) * (1.0f / NBIN);

    float v0 = 3.4e38f, v1 = 3.4e38f;
    int   i0 = 0,       i1 = 0;
    float worst = 3.4e38f;

    int lo = r, hi = r;
    bool ld = false, rd = false;
    while (!(ld && rd)) {
        if (!rd) {
            int pos = hi + lane;
            float cx = 3.4e38f, t = 3.4e38f; int sj = 0;
            if (pos < NN) {
                float4 cv = g_ss[pos];
                sj = g_sid[pos];
                cx = cv.x;
                t = fmaf(cv.x, m2x, fmaf(cv.y, m2y, fmaf(cv.z, m2z, cv.w)));
            }
            unsigned m = __ballot_sync(F, t < worst);
            while (m) {
                int s_ = __ffs(m) - 1; m &= m - 1;
                float tt = __shfl_sync(F, t, s_);
                int   jj = __shfl_sync(F, sj, s_);
                if (tt < worst) winsert(tt, jj, lane, v0, i0, v1, i1, worst);
            }
            float xe = __shfl_sync(F, cx, 31);
            float dx = xe - qx - binw;             // conservative: intra-bin disorder
            float wd2 = fmaf(worst + qw2, 1.0002f, 1e-6f);
            rd = (dx > 0.0f) && (dx * dx >= wd2);
            hi += 32;
        }
        if (!ld) {
            int pos = lo - 32 + lane;
            float cx = -3.4e38f, t = 3.4e38f; int sj = 0;
            if (pos >= 0) {
                float4 cv = g_ss[pos];
                sj = g_sid[pos];
                cx = cv.x;
                t = fmaf(cv.x, m2x, fmaf(cv.y, m2y, fmaf(cv.z, m2z, cv.w)));
            }
            unsigned m = __ballot_sync(F, t < worst);
            while (m) {
                int s_ = __ffs(m) - 1; m &= m - 1;
                float tt = __shfl_sync(F, t, s_);
                int   jj = __shfl_sync(F, sj, s_);
                if (tt < worst) winsert(tt, jj, lane, v0, i0, v1, i1, worst);
            }
            float xe = __shfl_sync(F, cx, 0);
            float dx = qx - xe - binw;             // conservative: intra-bin disorder
            float wd2 = fmaf(worst + qw2, 1.0002f, 1e-6f);
            ld = (dx > 0.0f) && (dx * dx >= wd2);
            lo -= 32;
        }
    }
    g_knn[Qo * KK + lane] = i0;
    if (lane < 8) g_knn[Qo * KK + 32 + lane] = i1;
}

// ---------------- K3a: edge weights + mean/max message aggregation ----------------
__global__ void __launch_bounds__(256) k_gather()
{
    __shared__ int   jl[4][KK];
    __shared__ float wl[4][KK];
    int tid = threadIdx.x;
    int g = tid >> 6, c = tid & 63;
    int i = blockIdx.x * 4 + g;
    if (c < KK) {
        int j = g_knn[i * KK + c];
        float4 sj = g_s4[j];
        float4 si_ = g_s4[i];
        float dx = si_.x - sj.x, dy = si_.y - sj.y, dz = si_.z - sj.z;
        float d2 = dx * dx + dy * dy + dz * dz;
        jl[g][c] = j;
        wl[g][c] = expf(-(d2 + 1e-6f));
    }
    __syncthreads();
    float sum = 0.f, mx = -3.4e38f;
#pragma unroll
    for (int k = 0; k < KK; k++) {
        float m = wl[g][k] * g_h[jl[g][k] * 64 + c];
        sum += m;
        mx = fmaxf(mx, m);
    }
    g_M[i * 128 + c] = sum * (1.0f / KK);
    g_M[i * 128 + 64 + c] = mx;
}

// ---------------- K3b: t = [mean|max|x] @ w_lin + b_lin + x ; BN2 partial sums ----------------
extern __shared__ char dynraw[];

__global__ void __launch_bounds__(256) k_lin(
    const float* __restrict__ x, const float* __restrict__ w_lin,
    const float* __restrict__ b_lin)
{
    float* wl = (float*)dynraw;              // [192*64]
    float* ar = (float*)dynraw + 192 * 64;   // [4][192]
    __shared__ float bl[64];
    __shared__ float red[2][4][64];
    int tid = threadIdx.x;
    for (int i = tid; i < 192 * 64; i += 256) wl[i] = w_lin[i];
    if (tid < 64) bl[tid] = b_lin[tid];
    __syncthreads();

    int c = tid & 63, sub = tid >> 6;
    int base = blockIdx.x * 128;
    float psum = 0.f, psq = 0.f;
    for (int it = 0; it < 32; it++) {
        int n = base + it * 4 + sub;
        ar[sub * 192 + c]       = g_M[n * 128 + c];
        ar[sub * 192 + 64 + c]  = g_M[n * 128 + 64 + c];
        ar[sub * 192 + 128 + c] = x[n * 64 + c];
        __syncthreads();
        float acc = bl[c] + ar[sub * 192 + 128 + c];   // + residual x
#pragma unroll
        for (int f = 0; f < 192; f++) acc = fmaf(ar[sub * 192 + f], wl[f * 64 + c], acc);
        g_t[n * 64 + c] = acc;
        psum += acc;
        psq = fmaf(acc, acc, psq);
        __syncthreads();
    }
    red[0][sub][c] = psum;
    red[1][sub][c] = psq;
    __syncthreads();
    if (sub == 0) {
        float s  = red[0][0][c] + red[0][1][c] + red[0][2][c] + red[0][3][c];
        float s2 = red[1][0][c] + red[1][1][c] + red[1][2][c] + red[1][3][c];
        atomicAdd(&g_sum2[c], s);
        atomicAdd(&g_sumsq2[c], s2);
    }
}

// ---------------- K4/K6: finalize BN affine params ----------------
__global__ void k_bnfin(const float* __restrict__ gamma, const float* __restrict__ beta, int which)
{
    int c = threadIdx.x;
    if (c < CC) {
        float s  = which ? g_sum3[c]   : g_sum2[c];
        float s2 = which ? g_sumsq3[c] : g_sumsq2[c];
        float mu  = s * (1.0f / NN);
        float var = s2 * (1.0f / NN) - mu * mu;
        float ai = gamma[c] * rsqrtf(var + 1e-5f);
        float bi = beta[c] - ai * mu;
        if (which) { g_a3[c] = ai; g_b3[c] = bi; }
        else       { g_a2[c] = ai; g_b2[c] = bi; }
    }
}

// ---------------- K5: y = BN2(t); z = elu(y@w_p1+b_p1)@w_p2+b_p2; u = y+z ; BN3 sums ----------------
__global__ void __launch_bounds__(256) k_mlp(
    const float* __restrict__ w_p1, const float* __restrict__ b_p1,
    const float* __restrict__ w_p2, const float* __restrict__ b_p2)
{
    __shared__ float w1[4096], w2[4096], b1s[64], b2s[64], aas[64], bbs[64];
    __shared__ float yr[4][64], vr[4][64];
    __shared__ float red[2][4][64];
    int tid = threadIdx.x;
    for (int i = tid; i < 4096; i += 256) { w1[i] = w_p1[i]; w2[i] = w_p2[i]; }
    if (tid < 64) { b1s[tid] = b_p1[tid]; b2s[tid] = b_p2[tid]; aas[tid] = g_a2[tid]; bbs[tid] = g_b2[tid]; }
    __syncthreads();

    int c = tid & 63, sub = tid >> 6;
    int base = blockIdx.x * 128;
    float psum = 0.f, psq = 0.f;
    for (int it = 0; it < 32; it++) {
        int n = base + it * 4 + sub;
        float yv = fmaf(aas[c], g_t[n * 64 + c], bbs[c]);
        yr[sub][c] = yv;
        __syncthreads();
        float a1 = b1s[c];
#pragma unroll
        for (int k = 0; k < 64; k++) a1 = fmaf(yr[sub][k], w1[k * 64 + c], a1);
        float v = a1 > 0.f ? a1 : expm1f(a1);
        vr[sub][c] = v;
        __syncthreads();
        float a2v = b2s[c];
#pragma unroll
        for (int k = 0; k < 64; k++) a2v = fmaf(vr[sub][k], w2[k * 64 + c], a2v);
        float u = yv + a2v;
        g_u[n * 64 + c] = u;
        psum += u;
        psq = fmaf(u, u, psq);
        __syncthreads();
    }
    red[0][sub][c] = psum;
    red[1][sub][c] = psq;
    __syncthreads();
    if (sub == 0) {
        float s  = red[0][0][c] + red[0][1][c] + red[0][2][c] + red[0][3][c];
        float s2 = red[1][0][c] + red[1][1][c] + red[1][2][c] + red[1][3][c];
        atomicAdd(&g_sum3[c], s);
        atomicAdd(&g_sumsq3[c], s2);
    }
}

// ---------------- K7: out = BN3(u) ----------------
__global__ void __launch_bounds__(256) k_out(float* __restrict__ out)
{
    int idx = blockIdx.x * 256 + threadIdx.x;   // over N*C/4 float4
    const float4* u4 = (const float4*)g_u;
    float4 v = u4[idx];
    int c = (idx * 4) & 63;
    float4 r;
    r.x = fmaf(g_a3[c + 0], v.x, g_b3[c + 0]);
    r.y = fmaf(g_a3[c + 1], v.y, g_b3[c + 1]);
    r.z = fmaf(g_a3[c + 2], v.z, g_b3[c + 2]);
    r.w = fmaf(g_a3[c + 3], v.w, g_b3[c + 3]);
    ((float4*)out)[idx] = r;
}

// ---------------- launch ----------------
extern "C" void kernel_launch(void* const* d_in, const int* in_sizes, int n_in,
                              void* d_out, int out_size)
{
    const float* x     = (const float*)d_in[0];
    const float* w_s   = (const float*)d_in[1];
    const float* w_h   = (const float*)d_in[2];
    const float* b_h   = (const float*)d_in[3];
    const float* w_lin = (const float*)d_in[4];
    const float* b_lin = (const float*)d_in[5];
    const float* w_p1  = (const float*)d_in[6];
    const float* b_p1  = (const float*)d_in[7];
    const float* w_p2  = (const float*)d_in[8];
    const float* b_p2  = (const float*)d_in[9];
    const float* gamma2 = (const float*)d_in[10];
    const float* beta2  = (const float*)d_in[11];
    const float* gamma3 = (const float*)d_in[12];
    const float* beta3  = (const float*)d_in[13];
    float* out = (float*)d_out;

    const int lin_smem = (192 * 64 + 4 * 192) * 4;       // 52224 B
    cudaFuncSetAttribute(k_lin, cudaFuncAttributeMaxDynamicSharedMemorySize, lin_smem);

    k_zero<<<1, NBIN>>>();
    k_proj<<<128, 256>>>(x, w_h, b_h, w_s);
    k_bins<<<NN / 256, 256>>>();
    k_scan<<<1, NBIN>>>();
    k_scatter<<<NN / 256, 256>>>();
    k_knn<<<NN / QW, 256>>>();
    k_gather<<<NN / 4, 256>>>();
    k_lin<<<128, 256, lin_smem>>>(x, w_lin, b_lin);
    k_bnfin<<<1, 64>>>(gamma2, beta2, 0);
    k_mlp<<<128, 256>>>(w_p1, b_p1, w_p2, b_p2);
    k_bnfin<<<1, 64>>>(gamma3, beta3, 1);
    k_out<<<(NN * CC / 4) / 256, 256>>>(out);
}